// round 9
// baseline (speedup 1.0000x reference)
#include <cuda_runtime.h>
#include <cstdint>

// CachedMPS on GB300 — HMMA tf32 3-term split, paired steps, m16 tiles.
// R9: 4 CTAs x 128 thr (independent barriers decorrelate ALU/MMA phases
// across CTAs on one SM), tt-outer gather (first MMA after 8 shuffles, not
// 32), pair scalars software-pipelined (x-only, computed during prev MMAs).

#define DEV_INLINE __device__ __forceinline__

static constexpr int D     = 32;
static constexpr int L     = 256;
static constexpr int NPAIR = 127;
static constexpr int C     = 10;
static constexpr int TPB   = 128;             // 4 warps x 16 rows = 64 rows/CTA
static constexpr int ROWS_PER_WARP = 16;
static constexpr int ROWS_PER_CTA  = TPB / 32 * ROWS_PER_WARP;   // 64
static constexpr float HALF_PI = 1.57079632679489662f;
static constexpr unsigned TF32_MASK = 0xFFFFE000u;

// composite-W scratch: [NPAIR][4096] fp32, fragment-native order
__device__ float g_Bt[(size_t)NPAIR * 4096];

DEV_INLINE unsigned smem_u32(const void* p) {
    unsigned r;
    asm("{ .reg .u64 t; cvta.to.shared.u64 t, %1; cvt.u32.u64 %0, t; }" : "=r"(r) : "l"(p));
    return r;
}
DEV_INLINE void cp16(unsigned dst, const void* src) {
    asm volatile("cp.async.cg.shared.global [%0], [%1], 16;" :: "r"(dst), "l"(src));
}
DEV_INLINE void cp_commit() { asm volatile("cp.async.commit_group;"); }
DEV_INLINE void cp_wait0()  { asm volatile("cp.async.wait_group 0;" ::: "memory"); }

DEV_INLINE void mma8(float* c, const unsigned* a, unsigned b0, unsigned b1) {
    asm("mma.sync.aligned.m16n8k8.row.col.f32.tf32.tf32.f32 "
        "{%0,%1,%2,%3}, {%4,%5,%6,%7}, {%8,%9}, {%0,%1,%2,%3};"
        : "+f"(c[0]), "+f"(c[1]), "+f"(c[2]), "+f"(c[3])
        : "r"(a[0]), "r"(a[1]), "r"(a[2]), "r"(a[3]), "r"(b0), "r"(b1));
}

DEV_INLINE void split(float v, unsigned& hi, unsigned& lo) {
    hi = __float_as_uint(v) & TF32_MASK;                 // exact tf32 truncate
    lo = __float_as_uint(v - __uint_as_float(hi));       // exact (Sterbenz)
}

// ---- prep: composite pair products, B-fragment-native order (R6-verified) ----
__global__ void prep_pairs(const float* __restrict__ cores_mid) {
    __shared__ float sW0[2048], sW1[2048];
    const int p = blockIdx.x;
    const float* s0 = cores_mid + (size_t)(2 * p) * 2048;
    const float* s1 = cores_mid + (size_t)(2 * p + 1) * 2048;
    for (int i = threadIdx.x; i < 2048; i += blockDim.x) { sW0[i] = s0[i]; sW1[i] = s1[i]; }
    __syncthreads();

    float* dst = g_Bt + (size_t)p * 4096;
    for (int i = threadIdx.x; i < 4096; i += blockDim.x) {
        const int s = i & 3, lane = (i >> 2) & 31, tp = i >> 7;
        const int t = tp >> 1, jp = tp & 1;
        const int j = 2 * jp + (s >> 1), reg = s & 1;
        const int q = lane & 3, g = lane >> 2;
        const int k = 8 * t + q + 4 * reg;
        const int c = 8 * j + g;
        const int ci = k >> 5, a = k & 31;
        const float* r0 = sW0 + (ci & 1) * 1024 + a * 32;
        const float* r1 = sW1 + (ci >> 1) * 1024 + c;
        float v = 0.f;
        #pragma unroll 8
        for (int cc = 0; cc < 32; cc++) v += r0[cc] * r1[cc * 32];
        dst[i] = v;
    }
}

__global__ void __launch_bounds__(TPB, 4)
mps_hmma_kernel(const float* __restrict__ x,
                const float* __restrict__ core0,
                const float* __restrict__ coreN,
                float* __restrict__ out, int B)
{
    __shared__ __align__(16) float sW[2][4096];   // 2 stages x 16KB (fp32 W)

    const int tid  = threadIdx.x;
    const int lane = tid & 31;
    const int w    = tid >> 5;
    const int q    = lane & 3;
    const int g    = lane >> 2;
    const int rowbase = blockIdx.x * ROWS_PER_CTA + w * ROWS_PER_WARP;

    int rows[2];
    rows[0] = min(rowbase + g,     B - 1);
    rows[1] = min(rowbase + g + 8, B - 1);

    // prefetch pair-0 tile (16KB = 1024 x 16B, 8 per thread)
    {
        const float* gsrc = g_Bt;
        const unsigned sb = smem_u32(&sW[0][0]);
        #pragma unroll
        for (int i = 0; i < 8; i++) {
            const int idx = tid + i * TPB;
            cp16(sb + idx * 16, gsrc + idx * 4);
        }
        cp_commit();
    }

    // ---- init acc = M0, c-frag layout: acc[4j+2rs+p] = M[g+8rs][8j+2q+p] ----
    float acc[16];
    #pragma unroll
    for (int rs = 0; rs < 2; rs++) {
        float s0, c0;
        __sincosf(HALF_PI * __ldg(x + (size_t)rows[rs] * L), &s0, &c0);
        #pragma unroll
        for (int j = 0; j < 4; j++)
            #pragma unroll
            for (int pp = 0; pp < 2; pp++) {
                const int col = 8 * j + 2 * q + pp;
                acc[4 * j + 2 * rs + pp] = c0 * core0[col] + s0 * core0[32 + col];
            }
    }

    // pair-0 scalars (x-only; pipelined thereafter)
    float sc[4][2];
    #pragma unroll
    for (int rs = 0; rs < 2; rs++) {
        float s1v, c1v, s2v, c2v;
        __sincosf(HALF_PI * __ldg(x + (size_t)rows[rs] * L + 1), &s1v, &c1v);
        __sincosf(HALF_PI * __ldg(x + (size_t)rows[rs] * L + 2), &s2v, &c2v);
        sc[0][rs] = c1v * c2v;  sc[1][rs] = s1v * c2v;
        sc[2][rs] = c1v * s2v;  sc[3][rs] = s1v * s2v;
    }

    // ---- 127 composite steps ----
    for (int p = 0; p < NPAIR; p++) {
        cp_wait0();
        __syncthreads();

        if (p + 1 < NPAIR) {
            const float* gsrc = g_Bt + (size_t)(p + 1) * 4096;
            const unsigned sb = smem_u32(&sW[(p + 1) & 1][0]);
            #pragma unroll
            for (int i = 0; i < 8; i++) {
                const int idx = tid + i * TPB;
                cp16(sb + idx * 16, gsrc + idx * 4);
            }
            cp_commit();
        }

        const float* W = &sW[p & 1][0];
        const int sl = 4 * g + (q >> 1);
        const bool odd = (q & 1);

        float nacc[16];
        #pragma unroll
        for (int k = 0; k < 16; k++) nacc[k] = 0.f;

        #pragma unroll
        for (int tt = 0; tt < 4; tt++) {
            // gather this k-tile's a-frag from c-frags (8 shuffles)
            float av[4];
            {
                const float v0a = __shfl_sync(0xffffffffu, acc[4 * tt],     sl);
                const float v1a = __shfl_sync(0xffffffffu, acc[4 * tt + 1], sl);
                const float v0b = __shfl_sync(0xffffffffu, acc[4 * tt + 2], sl);
                const float v1b = __shfl_sync(0xffffffffu, acc[4 * tt + 3], sl);
                const float w0a = __shfl_sync(0xffffffffu, acc[4 * tt],     sl + 2);
                const float w1a = __shfl_sync(0xffffffffu, acc[4 * tt + 1], sl + 2);
                const float w0b = __shfl_sync(0xffffffffu, acc[4 * tt + 2], sl + 2);
                const float w1b = __shfl_sync(0xffffffffu, acc[4 * tt + 3], sl + 2);
                av[0] = odd ? v1a : v0a;
                av[1] = odd ? v1b : v0b;
                av[2] = odd ? w1a : w0a;
                av[3] = odd ? w1b : w0b;
            }

            #pragma unroll
            for (int ci = 0; ci < 4; ci++) {
                const int t = 4 * ci + tt;
                const float4 w0 = *reinterpret_cast<const float4*>(W + ((t * 2 + 0) * 32 + lane) * 4);
                const float4 w1 = *reinterpret_cast<const float4*>(W + ((t * 2 + 1) * 32 + lane) * 4);

                unsigned bh[2][4], bl[2][4];
                split(w0.x, bh[0][0], bl[0][0]); split(w0.y, bh[0][1], bl[0][1]);
                split(w0.z, bh[0][2], bl[0][2]); split(w0.w, bh[0][3], bl[0][3]);
                split(w1.x, bh[1][0], bl[1][0]); split(w1.y, bh[1][1], bl[1][1]);
                split(w1.z, bh[1][2], bl[1][2]); split(w1.w, bh[1][3], bl[1][3]);

                unsigned ahi[4], alo[4];
                #pragma unroll
                for (int i = 0; i < 4; i++) {
                    const float v = av[i] * sc[ci][i & 1];
                    split(v, ahi[i], alo[i]);
                }

                #pragma unroll
                for (int j = 0; j < 4; j++) {
                    const int jp = j >> 1, e = (j & 1) * 2;
                    mma8(&nacc[4 * j], ahi, bh[jp][e], bh[jp][e + 1]);   // hi*Whi
                    mma8(&nacc[4 * j], ahi, bl[jp][e], bl[jp][e + 1]);   // hi*Wlo
                    mma8(&nacc[4 * j], alo, bh[jp][e], bh[jp][e + 1]);   // lo*Whi
                }
            }
        }

        // next pair's scalars (x-only; overlaps in-flight MMAs)
        if (p + 1 < NPAIR) {
            #pragma unroll
            for (int rs = 0; rs < 2; rs++) {
                float s1v, c1v, s2v, c2v;
                __sincosf(HALF_PI * __ldg(x + (size_t)rows[rs] * L + (2 * p + 3)), &s1v, &c1v);
                __sincosf(HALF_PI * __ldg(x + (size_t)rows[rs] * L + (2 * p + 4)), &s2v, &c2v);
                sc[0][rs] = c1v * c2v;  sc[1][rs] = s1v * c2v;
                sc[2][rs] = c1v * s2v;  sc[3][rs] = s1v * s2v;
            }
        }

        #pragma unroll
        for (int k = 0; k < 16; k++) acc[k] = nacc[k];

        // range control every 8 pairs (16 steps; R2-validated cadence)
        if ((p & 7) == 7) {
            #pragma unroll
            for (int rs = 0; rs < 2; rs++) {
                float ss = 0.f;
                #pragma unroll
                for (int j = 0; j < 4; j++) {
                    const float v0 = acc[4 * j + 2 * rs];
                    const float v1 = acc[4 * j + 2 * rs + 1];
                    ss += v0 * v0 + v1 * v1;
                }
                ss += __shfl_xor_sync(0xffffffffu, ss, 1);
                ss += __shfl_xor_sync(0xffffffffu, ss, 2);
                const float r = rsqrtf(ss);
                #pragma unroll
                for (int j = 0; j < 4; j++) {
                    acc[4 * j + 2 * rs]     *= r;
                    acc[4 * j + 2 * rs + 1] *= r;
                }
            }
        }
    }

    // ---- readout: eps-free unit normalize + coreN contraction ----
    #pragma unroll
    for (int rs = 0; rs < 2; rs++) {
        const int row = rowbase + g + 8 * rs;

        float ss = 0.f;
        #pragma unroll
        for (int j = 0; j < 4; j++) {
            const float v0 = acc[4 * j + 2 * rs];
            const float v1 = acc[4 * j + 2 * rs + 1];
            ss += v0 * v0 + v1 * v1;
        }
        ss += __shfl_xor_sync(0xffffffffu, ss, 1);
        ss += __shfl_xor_sync(0xffffffffu, ss, 2);
        const float inv = rsqrtf(ss);           // NO eps (R1 lesson)

        float sL, cL;
        __sincosf(HALF_PI * __ldg(x + (size_t)rows[rs] * L + (L - 1)), &sL, &cL);

        float lg[C];
        #pragma unroll
        for (int cc = 0; cc < C; cc++) lg[cc] = 0.f;
        #pragma unroll
        for (int j = 0; j < 4; j++)
            #pragma unroll
            for (int pp = 0; pp < 2; pp++) {
                const int col = 8 * j + 2 * q + pp;
                const float m = acc[4 * j + 2 * rs + pp];
                #pragma unroll
                for (int cc = 0; cc < C; cc++) {
                    const float wv = cL * coreN[col * C + cc]
                                   + sL * coreN[D * C + col * C + cc];
                    lg[cc] += m * wv;
                }
            }
        #pragma unroll
        for (int cc = 0; cc < C; cc++) {
            lg[cc] += __shfl_xor_sync(0xffffffffu, lg[cc], 1);
            lg[cc] += __shfl_xor_sync(0xffffffffu, lg[cc], 2);
        }
        if (q == 0 && row < B) {
            #pragma unroll
            for (int cc = 0; cc < C; cc++)
                out[(size_t)row * C + cc] = lg[cc] * inv;
        }
    }
}

extern "C" void kernel_launch(void* const* d_in, const int* in_sizes, int n_in,
                              void* d_out, int out_size)
{
    const float* x         = (const float*)d_in[0];
    const float* core0     = (const float*)d_in[1];
    const float* cores_mid = (const float*)d_in[2];
    const float* coreN     = (const float*)d_in[3];
    float* out = (float*)d_out;

    const int B = in_sizes[0] / L;
    const int grid = (B + ROWS_PER_CTA - 1) / ROWS_PER_CTA;   // 512 for B=32768

    prep_pairs<<<NPAIR, 256>>>(cores_mid);
    mps_hmma_kernel<<<grid, TPB>>>(x, core0, coreN, out, B);
}

// round 10
// speedup vs baseline: 1.6724x; 1.6724x over previous
#include <cuda_runtime.h>
#include <cuda_fp16.h>
#include <cstdint>

// CachedMPS on GB300 — fp16 m16n8k16 2-way-split HMMA chain, paired steps.
// R10: tf32 k8 -> f16 k16 halves MMA instruction count (the R7-R9 invariant
// limiter); A-frag relayout becomes register-direct (c-frag and a-frag cols
// live on the same thread for k16) so the shuffle gather is gone; B hi/lo
// pre-split+packed f16x2 in prep (zero runtime B ALU).
// Split: v = f32; hi = f16(v); lo' = f16(1024*(v - f32(hi))) (exact f32 sub,
// scaled so lo' is never subnormal). D = hi*hi (nacc) + [hi*lo' + lo'*hi]
// (clo); acc = nacc + clo/1024. Dropped lo*lo ~ 2^-22.

#define DEV_INLINE __device__ __forceinline__

static constexpr int D     = 32;
static constexpr int L     = 256;
static constexpr int NPAIR = 127;
static constexpr int C     = 10;
static constexpr int TPB   = 128;             // 4 warps x 16 rows = 64 rows/CTA
static constexpr int ROWS_PER_CTA = 64;
static constexpr float HALF_PI = 1.57079632679489662f;
static constexpr float LO_SCALE = 1024.0f;
static constexpr float LO_INV   = 1.0f / 1024.0f;

// composite-W scratch: [NPAIR][4096] u32 (f16x2-packed hi/lo, frag-native)
__device__ unsigned g_Bt[(size_t)NPAIR * 4096];

DEV_INLINE unsigned smem_u32(const void* p) {
    unsigned r;
    asm("{ .reg .u64 t; cvta.to.shared.u64 t, %1; cvt.u32.u64 %0, t; }" : "=r"(r) : "l"(p));
    return r;
}
DEV_INLINE void cp16(unsigned dst, const void* src) {
    asm volatile("cp.async.cg.shared.global [%0], [%1], 16;" :: "r"(dst), "l"(src));
}
DEV_INLINE void cp_commit() { asm volatile("cp.async.commit_group;"); }
DEV_INLINE void cp_wait0()  { asm volatile("cp.async.wait_group 0;" ::: "memory"); }

// pack two f32 into f16x2: lower half = first arg (first PTX src -> upper)
DEV_INLINE unsigned packh2(float lo, float hi) {
    unsigned r; asm("cvt.rn.f16x2.f32 %0, %1, %2;" : "=r"(r) : "f"(hi), "f"(lo));
    return r;
}
DEV_INLINE void unpackh2(unsigned u, float& lo, float& hi) {
    const __half2 h = *reinterpret_cast<const __half2*>(&u);
    lo = __low2float(h); hi = __high2float(h);
}

// m16n8k16 row.col f32.f16.f16.f32, accumulate in place
DEV_INLINE void mma16(float* c, const unsigned* a, unsigned b0, unsigned b1) {
    asm("mma.sync.aligned.m16n8k16.row.col.f32.f16.f16.f32 "
        "{%0,%1,%2,%3}, {%4,%5,%6,%7}, {%8,%9}, {%0,%1,%2,%3};"
        : "+f"(c[0]), "+f"(c[1]), "+f"(c[2]), "+f"(c[3])
        : "r"(a[0]), "r"(a[1]), "r"(a[2]), "r"(a[3]), "r"(b0), "r"(b1));
}

// ---- prep: composite pair products -> f16 hi/lo, B-frag-native, packed ----
// u32 slot i: s=i&3 (0=hi reg0,1=hi reg1,2=lo reg0,3=lo reg1), lane=(i>>2)&31,
// tj=i>>7: T=tj>>2 (k16-tile), j=tj&3 (n-tile). q=lane&3, g=lane>>2.
// reg r: k0 = 16T + 2q + 8r; pack {W[k0][n], W[k0+1][n]}, n = 8j+g.
// W[k][n], k=ci*32+a: sum_cc W0[ci&1][a][cc]*W1[ci>>1][cc][n].
__global__ void prep_pairs(const float* __restrict__ cores_mid) {
    __shared__ float sW0[2048], sW1[2048];
    const int p = blockIdx.x;
    const float* s0 = cores_mid + (size_t)(2 * p) * 2048;
    const float* s1 = cores_mid + (size_t)(2 * p + 1) * 2048;
    for (int i = threadIdx.x; i < 2048; i += blockDim.x) { sW0[i] = s0[i]; sW1[i] = s1[i]; }
    __syncthreads();

    unsigned* dst = g_Bt + (size_t)p * 4096;
    for (int i = threadIdx.x; i < 4096; i += blockDim.x) {
        const int s = i & 3, lane = (i >> 2) & 31, tj = i >> 7;
        const int T = tj >> 2, j = tj & 3;
        const int q = lane & 3, g = lane >> 2;
        const int reg = s & 1, term = s >> 1;
        const int k0 = 16 * T + 2 * q + 8 * reg;
        const int n  = 8 * j + g;

        float v[2];
        #pragma unroll
        for (int e = 0; e < 2; e++) {
            const int k = k0 + e, ci = k >> 5, a = k & 31;
            const float* r0 = sW0 + (ci & 1) * 1024 + a * 32;
            const float* r1 = sW1 + (ci >> 1) * 1024 + n;
            float acc = 0.f;
            #pragma unroll 8
            for (int cc = 0; cc < 32; cc++) acc += r0[cc] * r1[cc * 32];
            v[e] = acc;
        }
        const unsigned hi = packh2(v[0], v[1]);
        if (term == 0) {
            dst[i] = hi;
        } else {
            float h0, h1; unpackh2(hi, h0, h1);
            dst[i] = packh2(LO_SCALE * (v[0] - h0), LO_SCALE * (v[1] - h1));
        }
    }
}

__global__ void __launch_bounds__(TPB, 4)
mps_hmma_kernel(const float* __restrict__ x,
                const float* __restrict__ core0,
                const float* __restrict__ coreN,
                float* __restrict__ out, int B)
{
    __shared__ __align__(16) unsigned sW[2][4096];   // 2 stages x 16KB

    const int tid  = threadIdx.x;
    const int lane = tid & 31;
    const int w    = tid >> 5;
    const int q    = lane & 3;
    const int g    = lane >> 2;
    const int rowbase = blockIdx.x * ROWS_PER_CTA + w * 16;

    int rows[2];
    rows[0] = min(rowbase + g,     B - 1);
    rows[1] = min(rowbase + g + 8, B - 1);

    // prefetch pair-0 tile (16KB)
    {
        const unsigned* gsrc = g_Bt;
        const unsigned sb = smem_u32(&sW[0][0]);
        #pragma unroll
        for (int i = 0; i < 8; i++) {
            const int idx = tid + i * TPB;
            cp16(sb + idx * 16, gsrc + idx * 4);
        }
        cp_commit();
    }

    // ---- init acc = M0, c-frag layout: acc[4j+2rs+p] = M[g+8rs][8j+2q+p] ----
    float acc[16];
    #pragma unroll
    for (int rs = 0; rs < 2; rs++) {
        float s0, c0;
        __sincosf(HALF_PI * __ldg(x + (size_t)rows[rs] * L), &s0, &c0);
        #pragma unroll
        for (int j = 0; j < 4; j++)
            #pragma unroll
            for (int pp = 0; pp < 2; pp++) {
                const int col = 8 * j + 2 * q + pp;
                acc[4 * j + 2 * rs + pp] = c0 * core0[col] + s0 * core0[32 + col];
            }
    }

    // pair-0 scalars (x-only; pipelined thereafter)
    float sc[4][2];
    #pragma unroll
    for (int rs = 0; rs < 2; rs++) {
        float s1v, c1v, s2v, c2v;
        __sincosf(HALF_PI * __ldg(x + (size_t)rows[rs] * L + 1), &s1v, &c1v);
        __sincosf(HALF_PI * __ldg(x + (size_t)rows[rs] * L + 2), &s2v, &c2v);
        sc[0][rs] = c1v * c2v;  sc[1][rs] = s1v * c2v;
        sc[2][rs] = c1v * s2v;  sc[3][rs] = s1v * s2v;
    }

    // ---- 127 composite steps ----
    for (int p = 0; p < NPAIR; p++) {
        cp_wait0();
        __syncthreads();

        if (p + 1 < NPAIR) {
            const unsigned* gsrc = g_Bt + (size_t)(p + 1) * 4096;
            const unsigned sb = smem_u32(&sW[(p + 1) & 1][0]);
            #pragma unroll
            for (int i = 0; i < 8; i++) {
                const int idx = tid + i * TPB;
                cp16(sb + idx * 16, gsrc + idx * 4);
            }
            cp_commit();
        }

        const unsigned* W = &sW[p & 1][0];

        float nacc[16], clo[16];
        #pragma unroll
        for (int k = 0; k < 16; k++) { nacc[k] = 0.f; clo[k] = 0.f; }

        #pragma unroll
        for (int T = 0; T < 8; T++) {
            const int ci = T >> 1;
            const int j1 = 2 * (T & 1), j2 = j1 + 1;
            const float sc0 = sc[ci][0], sc1 = sc[ci][1];

            // A-frag: register-direct from c-frag (no shuffles!)
            const float v00 = sc0 * acc[4 * j1 + 0], v01 = sc0 * acc[4 * j1 + 1];
            const float v10 = sc1 * acc[4 * j1 + 2], v11 = sc1 * acc[4 * j1 + 3];
            const float v20 = sc0 * acc[4 * j2 + 0], v21 = sc0 * acc[4 * j2 + 1];
            const float v30 = sc1 * acc[4 * j2 + 2], v31 = sc1 * acc[4 * j2 + 3];

            unsigned ahi[4], alo[4];
            ahi[0] = packh2(v00, v01); ahi[1] = packh2(v10, v11);
            ahi[2] = packh2(v20, v21); ahi[3] = packh2(v30, v31);
            {
                float h0, h1;
                unpackh2(ahi[0], h0, h1);
                alo[0] = packh2(LO_SCALE * (v00 - h0), LO_SCALE * (v01 - h1));
                unpackh2(ahi[1], h0, h1);
                alo[1] = packh2(LO_SCALE * (v10 - h0), LO_SCALE * (v11 - h1));
                unpackh2(ahi[2], h0, h1);
                alo[2] = packh2(LO_SCALE * (v20 - h0), LO_SCALE * (v21 - h1));
                unpackh2(ahi[3], h0, h1);
                alo[3] = packh2(LO_SCALE * (v30 - h0), LO_SCALE * (v31 - h1));
            }

            #pragma unroll
            for (int j = 0; j < 4; j++) {
                const uint4 b = *reinterpret_cast<const uint4*>(
                    W + ((size_t)(T * 4 + j) * 32 + lane) * 4);
                mma16(&nacc[4 * j], ahi, b.x, b.y);   // hi*Bhi
                mma16(&clo[4 * j],  ahi, b.z, b.w);   // hi*Blo'
                mma16(&clo[4 * j],  alo, b.x, b.y);   // lo'*Bhi
            }
        }

        // next pair's scalars (x-only; overlaps in-flight MMAs)
        if (p + 1 < NPAIR) {
            #pragma unroll
            for (int rs = 0; rs < 2; rs++) {
                float s1v, c1v, s2v, c2v;
                __sincosf(HALF_PI * __ldg(x + (size_t)rows[rs] * L + (2 * p + 3)), &s1v, &c1v);
                __sincosf(HALF_PI * __ldg(x + (size_t)rows[rs] * L + (2 * p + 4)), &s2v, &c2v);
                sc[0][rs] = c1v * c2v;  sc[1][rs] = s1v * c2v;
                sc[2][rs] = c1v * s2v;  sc[3][rs] = s1v * s2v;
            }
        }

        // fold scaled correction back
        #pragma unroll
        for (int k = 0; k < 16; k++) acc[k] = fmaf(clo[k], LO_INV, nacc[k]);

        // range control every 4 pairs (keeps f16 hi terms in normal range)
        if ((p & 3) == 3) {
            #pragma unroll
            for (int rs = 0; rs < 2; rs++) {
                float ss = 0.f;
                #pragma unroll
                for (int j = 0; j < 4; j++) {
                    const float v0 = acc[4 * j + 2 * rs];
                    const float v1 = acc[4 * j + 2 * rs + 1];
                    ss += v0 * v0 + v1 * v1;
                }
                ss += __shfl_xor_sync(0xffffffffu, ss, 1);
                ss += __shfl_xor_sync(0xffffffffu, ss, 2);
                const float r = rsqrtf(ss);
                #pragma unroll
                for (int j = 0; j < 4; j++) {
                    acc[4 * j + 2 * rs]     *= r;
                    acc[4 * j + 2 * rs + 1] *= r;
                }
            }
        }
    }

    // ---- readout: eps-free unit normalize + coreN contraction ----
    #pragma unroll
    for (int rs = 0; rs < 2; rs++) {
        const int row = rowbase + g + 8 * rs;

        float ss = 0.f;
        #pragma unroll
        for (int j = 0; j < 4; j++) {
            const float v0 = acc[4 * j + 2 * rs];
            const float v1 = acc[4 * j + 2 * rs + 1];
            ss += v0 * v0 + v1 * v1;
        }
        ss += __shfl_xor_sync(0xffffffffu, ss, 1);
        ss += __shfl_xor_sync(0xffffffffu, ss, 2);
        const float inv = rsqrtf(ss);           // NO eps (R1 lesson)

        float sL, cL;
        __sincosf(HALF_PI * __ldg(x + (size_t)rows[rs] * L + (L - 1)), &sL, &cL);

        float lg[C];
        #pragma unroll
        for (int cc = 0; cc < C; cc++) lg[cc] = 0.f;
        #pragma unroll
        for (int j = 0; j < 4; j++)
            #pragma unroll
            for (int pp = 0; pp < 2; pp++) {
                const int col = 8 * j + 2 * q + pp;
                const float m = acc[4 * j + 2 * rs + pp];
                #pragma unroll
                for (int cc = 0; cc < C; cc++) {
                    const float wv = cL * coreN[col * C + cc]
                                   + sL * coreN[D * C + col * C + cc];
                    lg[cc] += m * wv;
                }
            }
        #pragma unroll
        for (int cc = 0; cc < C; cc++) {
            lg[cc] += __shfl_xor_sync(0xffffffffu, lg[cc], 1);
            lg[cc] += __shfl_xor_sync(0xffffffffu, lg[cc], 2);
        }
        if (q == 0 && row < B) {
            #pragma unroll
            for (int cc = 0; cc < C; cc++)
                out[(size_t)row * C + cc] = lg[cc] * inv;
        }
    }
}

extern "C" void kernel_launch(void* const* d_in, const int* in_sizes, int n_in,
                              void* d_out, int out_size)
{
    const float* x         = (const float*)d_in[0];
    const float* core0     = (const float*)d_in[1];
    const float* cores_mid = (const float*)d_in[2];
    const float* coreN     = (const float*)d_in[3];
    float* out = (float*)d_out;

    const int B = in_sizes[0] / L;
    const int grid = (B + ROWS_PER_CTA - 1) / ROWS_PER_CTA;   // 512 for B=32768

    prep_pairs<<<NPAIR, 256>>>(cores_mid);
    mps_hmma_kernel<<<grid, TPB>>>(x, core0, coreN, out, B);
}